// round 5
// baseline (speedup 1.0000x reference)
#include <cuda_runtime.h>
#include <cuda_bf16.h>

// Problem constants: B=1, H=2, S=128, D=64
#define Sdim 128
#define Ddim 64
#define Hdim 2
#define TWOD 128          // 2*D
#define DD   4096         // D*D
#define ROWS (Hdim * Sdim)   // 256 (h, s) pairs

typedef unsigned long long ull;

// Scratch (device globals; no allocation allowed)
__device__ float g_A [ROWS * TWOD];   // Q @ W1[:D]            (256 x 128)
__device__ float g_Bk[ROWS * TWOD];   // K @ W1[D:] + b1       (256 x 128)
__device__ float g_T [ROWS * TWOD];   // sum_i tanh(A_i + Bk_j) (256 x 128)

__device__ __forceinline__ float tanh_approx(float x) {
    float y;
    asm("tanh.approx.f32 %0, %1;" : "=f"(y) : "f"(x));
    return y;
}
__device__ __forceinline__ ull fma2(ull a, ull b, ull c) {
    ull d;
    asm("fma.rn.f32x2 %0, %1, %2, %3;" : "=l"(d) : "l"(a), "l"(b), "l"(c));
    return d;
}
__device__ __forceinline__ ull pack2(float x, float y) {
    ull r;
    asm("mov.b64 %0, {%1, %2};" : "=l"(r) : "f"(x), "f"(y));
    return r;
}
__device__ __forceinline__ void unpack2(ull v, float& x, float& y) {
    asm("mov.b64 {%0, %1}, %2;" : "=f"(x), "=f"(y) : "l"(v));
}

// ---------------------------------------------------------------------------
// K1: tiled tiny-GEMM.  A = Q @ W1[0:64,:],  Bk = K @ W1[64:128,:] + b1.
// Block tile: 16 rows x 64 cols, K=64.  grid 64 = rtile(16) x ctile(2) x {A,Bk}.
// 256 threads: trow = t>>4 (16 rows), tcol = t&15 (4 cols each).
// ---------------------------------------------------------------------------
__global__ void __launch_bounds__(256, 6)
k1_proj(const float* __restrict__ Q, const float* __restrict__ Kin,
        const float* __restrict__ W1, const float* __restrict__ b1) {
    __shared__ float x_s[16 * Ddim];          // 16 input rows x 64
    int b = blockIdx.x;
    bool isB = (b & 1);
    int ctile = (b >> 1) & 1;
    int rtile = b >> 2;                       // 0..15
    int t = threadIdx.x;
    int trow = t >> 4;                        // 0..15
    int tcol = t & 15;                        // 0..15 -> 4 cols

    const float* src = (isB ? Kin : Q) + rtile * 16 * Ddim;
    const float* W = W1 + (isB ? Ddim * TWOD : 0) + ctile * 64;

    // stage 16 x 64 input rows: one float4 per thread
    ((float4*)x_s)[t] = ((const float4*)src)[t];
    __syncthreads();

    int c0 = tcol * 4;
    float4 acc;
    if (isB) acc = *(const float4*)(b1 + ctile * 64 + c0);
    else     acc = make_float4(0.f, 0.f, 0.f, 0.f);

    const float* xr = x_s + trow * Ddim;
#pragma unroll 8
    for (int k = 0; k < Ddim; k++) {
        float4 w = *(const float4*)(W + k * TWOD + c0);
        float x = xr[k];
        acc.x = fmaf(x, w.x, acc.x);
        acc.y = fmaf(x, w.y, acc.y);
        acc.z = fmaf(x, w.z, acc.z);
        acc.w = fmaf(x, w.w, acc.w);
    }
    float* dst = (isB ? g_Bk : g_A) + (rtile * 16 + trow) * TWOD + ctile * 64 + c0;
    *(float4*)dst = acc;
}

// ---------------------------------------------------------------------------
// K2: T[r,c] = sum_i tanh(A[h,i,c] + Bk[r,c]),  r = h*128 + j   (proven fast)
// grid 256 x 128. 8 loads batched ahead of the MUFU.TANH chain.
// ---------------------------------------------------------------------------
__global__ void __launch_bounds__(128, 4) k2_tanh_reduce() {
    int r = blockIdx.x;                  // (h, j)
    int c = threadIdx.x;
    int h = r >> 7;
    float bk = g_Bk[r * TWOD + c];
    const float* Abase = g_A + h * Sdim * TWOD + c;
    float acc0 = 0.f, acc1 = 0.f, acc2 = 0.f, acc3 = 0.f;
#pragma unroll
    for (int i = 0; i < Sdim; i += 8) {
        float a0 = Abase[(i + 0) * TWOD];
        float a1 = Abase[(i + 1) * TWOD];
        float a2 = Abase[(i + 2) * TWOD];
        float a3 = Abase[(i + 3) * TWOD];
        float a4 = Abase[(i + 4) * TWOD];
        float a5 = Abase[(i + 5) * TWOD];
        float a6 = Abase[(i + 6) * TWOD];
        float a7 = Abase[(i + 7) * TWOD];
        acc0 += tanh_approx(a0 + bk);
        acc1 += tanh_approx(a1 + bk);
        acc2 += tanh_approx(a2 + bk);
        acc3 += tanh_approx(a3 + bk);
        acc0 += tanh_approx(a4 + bk);
        acc1 += tanh_approx(a5 + bk);
        acc2 += tanh_approx(a6 + bk);
        acc3 += tanh_approx(a7 + bk);
    }
    g_T[r * TWOD + c] = (acc0 + acc1) + (acc2 + acc3);
}

// ---------------------------------------------------------------------------
// K3 (fused, f32x2, high-occ): U-tile = T @ W2 in packed m-pair registers,
// contracted against K in epilogue:
//   out[m, d=bn] = sum_e (Utile[m,e]/S + b2[d*64+e]) * K[m,e]
// M=256, N=4096, K=128.  BM=64, BN=64 (one d per block), BK=32.
// 256 threads: tx = t&15 -> 4 e-cols; ty = t>>4 (16) -> 4 m-rows (2 pairs).
// Per kk: 1 LDS.128 (a: 4 m) + 2 LDS.128 (b: duplicated W2 pairs) + 8 fma2.
// W2 staged pre-duplicated: Ws2a[kk][tx] = {w0,w0,w1,w1},
//                           Ws2b[kk][tx] = {w2,w2,w3,w3}  (conflict-free).
// grid: (64, 4).
// ---------------------------------------------------------------------------
#define TS 68   // Tst row stride (floats): 272B = 17*16B -> 16B-aligned rows
#define KS 68

__global__ void __launch_bounds__(256, 4)
k3_gemm_fused(const float* __restrict__ W2,
              const float* __restrict__ Kin,
              const float* __restrict__ b2,
              float* __restrict__ out) {
    __shared__ float Tst [32 * TS];       // [kk][m] transposed T tile
    __shared__ float Ws2a[32 * 64];       // [kk][16 tx][4] duplicated pairs
    __shared__ float Ws2b[32 * 64];
    __shared__ float Kst [64 * KS];       // [e][m] transposed K rows
    int bm = blockIdx.y, bn = blockIdx.x;
    int tid = threadIdx.x;                // 0..255
    int tx = tid & 15;                    // e-group (4 cols)
    int ty = tid >> 4;                    // m-group (4 rows = 2 pairs)

    // Stage K rows (transposed): 64 m x 64 e -> Kst[e][m]
#pragma unroll
    for (int v = 0; v < 4; v++) {
        int i4 = tid + v * 256;           // 1024 float4
        int m = i4 >> 4, e4 = i4 & 15;
        float4 f = *(const float4*)(Kin + (bm * 64 + m) * Ddim + e4 * 4);
        Kst[(e4 * 4 + 0) * KS + m] = f.x;
        Kst[(e4 * 4 + 1) * KS + m] = f.y;
        Kst[(e4 * 4 + 2) * KS + m] = f.z;
        Kst[(e4 * 4 + 3) * KS + m] = f.w;
    }

    ull acc[2][4];
#pragma unroll
    for (int p = 0; p < 2; p++)
#pragma unroll
        for (int c = 0; c < 4; c++) acc[p][c] = 0ull;

#pragma unroll
    for (int kt = 0; kt < 4; kt++) {
        // stage T tile transposed: g_T[m][kt*32+k] -> Tst[k][m]
#pragma unroll
        for (int v = 0; v < 2; v++) {
            int i4 = tid + v * 256;       // 512 float4
            int m = i4 >> 3, kq = i4 & 7;
            float4 f = *(const float4*)(g_T + (bm * 64 + m) * TWOD + kt * 32 + kq * 4);
            Tst[(kq * 4 + 0) * TS + m] = f.x;
            Tst[(kq * 4 + 1) * TS + m] = f.y;
            Tst[(kq * 4 + 2) * TS + m] = f.z;
            Tst[(kq * 4 + 3) * TS + m] = f.w;
        }
        // stage W2 tile duplicated: 32 k x 64 n
#pragma unroll
        for (int v = 0; v < 2; v++) {
            int i4 = tid + v * 256;       // 512 float4
            int kk = i4 >> 4, n4 = i4 & 15;
            float4 f = *(const float4*)(W2 + (kt * 32 + kk) * DD + bn * 64 + n4 * 4);
            float4* pa = (float4*)(Ws2a + kk * 64 + n4 * 4);
            float4* pb = (float4*)(Ws2b + kk * 64 + n4 * 4);
            *pa = make_float4(f.x, f.x, f.y, f.y);
            *pb = make_float4(f.z, f.z, f.w, f.w);
        }
        __syncthreads();

#pragma unroll
        for (int kk = 0; kk < 32; kk++) {
            ulonglong2 av = *(const ulonglong2*)(Tst + kk * TS + ty * 4);
            ulonglong2 b01 = *(const ulonglong2*)(Ws2a + kk * 64 + tx * 4);
            ulonglong2 b23 = *(const ulonglong2*)(Ws2b + kk * 64 + tx * 4);
            acc[0][0] = fma2(av.x, b01.x, acc[0][0]);
            acc[0][1] = fma2(av.x, b01.y, acc[0][1]);
            acc[0][2] = fma2(av.x, b23.x, acc[0][2]);
            acc[0][3] = fma2(av.x, b23.y, acc[0][3]);
            acc[1][0] = fma2(av.y, b01.x, acc[1][0]);
            acc[1][1] = fma2(av.y, b01.y, acc[1][1]);
            acc[1][2] = fma2(av.y, b23.x, acc[1][2]);
            acc[1][3] = fma2(av.y, b23.y, acc[1][3]);
        }
        __syncthreads();
    }

    // Epilogue: v = acc/S + b2 ; pairwise dot with K over e; 16-lane reduce.
    const float invS = 1.0f / (float)Sdim;
    ull invS2 = pack2(invS, invS);
    float4 bbv = *(const float4*)(b2 + bn * 64 + tx * 4);
    ull bb[4] = { pack2(bbv.x, bbv.x), pack2(bbv.y, bbv.y),
                  pack2(bbv.z, bbv.z), pack2(bbv.w, bbv.w) };
#pragma unroll
    for (int p = 0; p < 2; p++) {
        ull sum = 0ull;
#pragma unroll
        for (int c = 0; c < 4; c++) {
            ull v = fma2(acc[p][c], invS2, bb[c]);
            ull kv = *(const ull*)(Kst + (tx * 4 + c) * KS + ty * 4 + 2 * p);
            sum = fma2(v, kv, sum);
        }
        float s0, s1;
        unpack2(sum, s0, s1);
#pragma unroll
        for (int off = 1; off < 16; off <<= 1) {
            s0 += __shfl_xor_sync(0xffffffffu, s0, off, 32);
            s1 += __shfl_xor_sync(0xffffffffu, s1, off, 32);
        }
        if (tx == 0) {
            int m0 = bm * 64 + ty * 4 + 2 * p;
            out[m0 * Ddim + bn] = s0;
            out[(m0 + 1) * Ddim + bn] = s1;
        }
    }
}

// ---------------------------------------------------------------------------
extern "C" void kernel_launch(void* const* d_in, const int* in_sizes, int n_in,
                              void* d_out, int out_size) {
    const float* Q   = (const float*)d_in[0];
    const float* Kin = (const float*)d_in[1];
    const float* W1  = (const float*)d_in[2];
    const float* b1  = (const float*)d_in[3];
    const float* W2  = (const float*)d_in[4];
    const float* b2  = (const float*)d_in[5];
    float* out = (float*)d_out;

    k1_proj<<<64, 256>>>(Q, Kin, W1, b1);
    k2_tanh_reduce<<<ROWS, TWOD>>>();
    k3_gemm_fused<<<dim3(Ddim, ROWS / 64), 256>>>(W2, Kin, b2, out);
}